// round 15
// baseline (speedup 1.0000x reference)
#include <cuda_runtime.h>
#include <cuda_fp16.h>
#include <cstdint>

constexpr int N = 50000;     // nodes
constexpr int E = 800000;    // edges
constexpr int K = 128;       // feature dim
constexpr int PAD = 96;      // padded CSR row stride

// ---------------- device scratch ----------------
__device__ __align__(16) __half g_yh[(size_t)N * K];   // GEMM output (fp16)
__device__ __align__(16) __half g_h16[(size_t)N * K];  // activations (fp16)
__device__ int   g_deg[N];
__device__ int   g_csr[(size_t)N * PAD];               // padded CSR (19.2 MB)
// W fp16: W1(16384) W2(16384) W3(8192)
__device__ __align__(16) __half g_W16[40960];

// ---------------- helpers ----------------
__device__ __forceinline__ uint32_t smem_u32(const void* p) {
    uint32_t a;
    asm("{ .reg .u64 t; cvta.to.shared.u64 t, %1; cvt.u32.u64 %0, t; }" : "=r"(a) : "l"(p));
    return a;
}

#define LDMX4(r0, r1, r2, r3, addr)                                            \
    asm volatile("ldmatrix.sync.aligned.m8n8.x4.shared.b16 {%0,%1,%2,%3}, [%4];" \
                 : "=r"(r0), "=r"(r1), "=r"(r2), "=r"(r3) : "r"(addr))

#define MMAF16(d, a, b)                                                         \
    asm volatile("mma.sync.aligned.m16n8k16.row.col.f32.f16.f16.f32 "            \
                 "{%0,%1,%2,%3}, {%4,%5,%6,%7}, {%8,%9}, {%0,%1,%2,%3};"         \
                 : "+f"((d)[0]), "+f"((d)[1]), "+f"((d)[2]), "+f"((d)[3])        \
                 : "r"((a)[0]), "r"((a)[1]), "r"((a)[2]), "r"((a)[3]),           \
                   "r"((b)[0]), "r"((b)[1]))

// ---------------- W convert (main stream) ----------------
__global__ void wsplit_kernel(const float* __restrict__ W1,
                              const float* __restrict__ W2,
                              const float* __restrict__ W3) {
    int i = blockIdx.x * blockDim.x + threadIdx.x;
    if (i < 40960) {
        float v;
        if (i < 16384) v = W1[i];
        else if (i < 32768) v = W2[i - 16384];
        else v = W3[i - 32768];
        g_W16[i] = __float2half_rn(v);
    }
}

// ---------------- deg zero (stream2) ----------------
__global__ void zero_deg_kernel() {
    int i = blockIdx.x * blockDim.x + threadIdx.x;
    if (i < N) g_deg[i] = 0;
}

// single edge pass: degree count + padded CSR scatter in one atomic
__global__ void fill_pad_kernel(const int4* __restrict__ src4,
                                const int4* __restrict__ dst4) {
    int t = blockIdx.x * blockDim.x + threadIdx.x;
    if (t < E / 4) {
        int4 d = __ldg(dst4 + t);
        int4 s = __ldg(src4 + t);
        int p0 = atomicAdd(&g_deg[d.x], 1);
        int p1 = atomicAdd(&g_deg[d.y], 1);
        int p2 = atomicAdd(&g_deg[d.z], 1);
        int p3 = atomicAdd(&g_deg[d.w], 1);
        if (p0 < PAD) g_csr[(size_t)d.x * PAD + p0] = s.x;
        if (p1 < PAD) g_csr[(size_t)d.y * PAD + p1] = s.y;
        if (p2 < PAD) g_csr[(size_t)d.z * PAD + p2] = s.z;
        if (p3 < PAD) g_csr[(size_t)d.w * PAD + p3] = s.w;
    }
}

// ---------------- HMMA GEMM: Yh = fp16( H @ W^T ), single fp16 W ----------------
constexpr int PITCH = 136;               // fp16 elems per smem row
constexpr int A_TILE = 128 * PITCH * 2;  // 34816 bytes

template <int DOUT, bool SRC32>
__global__ __launch_bounds__(256)
void mma_gemm_kernel(const void* __restrict__ Hin,
                     const __half* __restrict__ Wm,
                     __half* __restrict__ Yh) {
    constexpr int OFF_A = 0;
    constexpr int OFF_B = A_TILE;
    constexpr int NT = DOUT / 16;
    constexpr int NG = NT / 2;

    extern __shared__ char smem[];
    uint32_t sb = smem_u32(smem);
    int tid = threadIdx.x;
    int lane = tid & 31;
    int wid = tid >> 5;
    int wm = wid & 3;
    int wn = wid >> 2;
    int base = blockIdx.x * 128;

    for (int p = tid; p < 128 * 64; p += 256) {
        int r = p >> 6;
        int c2 = p & 63;
        int node = base + r;
        uint32_t w = 0;
        if (node < N) {
            if (SRC32) {
                float2 v = *(const float2*)((const float*)Hin + (size_t)node * K + c2 * 2);
                __half2 h2 = __floats2half2_rn(v.x, v.y);
                w = *(uint32_t*)&h2;
            } else {
                w = ((const uint32_t*)Hin)[(size_t)node * 64 + c2];
            }
        }
        *(uint32_t*)(smem + OFF_A + (r * PITCH + c2 * 2) * 2) = w;
    }
    for (int p = tid; p < DOUT * 64; p += 256) {
        int r = p >> 6;
        int c2 = p & 63;
        *(uint32_t*)(smem + OFF_B + (r * PITCH + c2 * 2) * 2) = ((const uint32_t*)Wm)[p];
    }
    __syncthreads();

    int m = lane >> 3;
    int lr = lane & 7;
    int rb = wm * 32;
    int nb = wn * (DOUT / 2);

    uint32_t aoff0 = (uint32_t)(((rb + lr + (m & 1) * 8) * PITCH + (m >> 1) * 8) * 2);
    uint32_t aoff1 = aoff0 + 16 * PITCH * 2;
    uint32_t boff[NG];
#pragma unroll
    for (int g = 0; g < NG; g++)
        boff[g] = (uint32_t)(((nb + 16 * g + lr + (m >> 1) * 8) * PITCH + (m & 1) * 8) * 2);

    float acc[2][NT][4];
#pragma unroll
    for (int mt = 0; mt < 2; mt++)
#pragma unroll
        for (int nt = 0; nt < NT; nt++)
#pragma unroll
            for (int q = 0; q < 4; q++) acc[mt][nt][q] = 0.f;

#pragma unroll
    for (int j = 0; j < 8; j++) {
        uint32_t kb = j * 32;
        uint32_t a[2][4], b[NT][2];
        LDMX4(a[0][0], a[0][1], a[0][2], a[0][3], sb + OFF_A + aoff0 + kb);
        LDMX4(a[1][0], a[1][1], a[1][2], a[1][3], sb + OFF_A + aoff1 + kb);
#pragma unroll
        for (int g = 0; g < NG; g++) {
            LDMX4(b[2 * g][0], b[2 * g][1], b[2 * g + 1][0], b[2 * g + 1][1],
                  sb + OFF_B + boff[g] + kb);
        }
#pragma unroll
        for (int mt = 0; mt < 2; mt++)
#pragma unroll
            for (int nt = 0; nt < NT; nt++)
                MMAF16(acc[mt][nt], a[mt], b[nt]);
    }

    int r0 = base + rb + (lane >> 2);
#pragma unroll
    for (int mt = 0; mt < 2; mt++) {
        int row = r0 + 16 * mt;
#pragma unroll
        for (int nt = 0; nt < NT; nt++) {
            int col = nb + 8 * nt + 2 * (lane & 3);
            if (row < N) {
                __half2 h = __floats2half2_rn(acc[mt][nt][0], acc[mt][nt][1]);
                *(__half2*)(Yh + (size_t)row * DOUT + col) = h;
            }
            if (row + 8 < N) {
                __half2 h = __floats2half2_rn(acc[mt][nt][2], acc[mt][nt][3]);
                *(__half2*)(Yh + (size_t)(row + 8) * DOUT + col) = h;
            }
        }
    }
}

// ---------------- aggregation ----------------
__device__ __forceinline__ void acc_tree(float& a0, float& a1,
                                         uint32_t w0, uint32_t w1,
                                         uint32_t w2, uint32_t w3) {
    __half2 h0 = __hadd2(*(__half2*)&w0, *(__half2*)&w1);
    __half2 h1 = __hadd2(*(__half2*)&w2, *(__half2*)&w3);
    __half2 h  = __hadd2(h0, h1);
    float2 f = __half22float2(h);
    a0 += f.x; a1 += f.y;
}

__device__ __forceinline__ void acc_h4(float& a0, float& a1, float& a2, float& a3, uint2 u) {
    float2 f0 = __half22float2(*(__half2*)&u.x);
    float2 f1 = __half22float2(*(__half2*)&u.y);
    a0 += f0.x; a1 += f0.y; a2 += f1.x; a3 += f1.y;
}

__global__ void agg128_kernel(__half* __restrict__ hout) {
    int gid = blockIdx.x * blockDim.x + threadIdx.x;
    int node = gid >> 5;
    int lane = gid & 31;
    if (node >= N) return;
    const uint2* yp = (const uint2*)g_yh;
    size_t start = (size_t)node * PAD;
    int d = g_deg[node];

    float a0 = 0, a1 = 0, a2 = 0, a3 = 0;
    float b0 = 0, b1 = 0, b2 = 0, b3 = 0;
    float c0 = 0, c1 = 0, c2 = 0, c3 = 0;
    float e0 = 0, e1 = 0, e2 = 0, e3 = 0;

    acc_h4(a0, a1, a2, a3, __ldg(yp + (size_t)node * 32 + lane));   // self (fp32)

    int j = 0;
    for (; j + 16 <= d; j += 16) {
        const int* cs = g_csr + start + j;
        uint2 u0 = __ldg(yp + (size_t)cs[0] * 32 + lane);
        uint2 u1 = __ldg(yp + (size_t)cs[1] * 32 + lane);
        uint2 u2 = __ldg(yp + (size_t)cs[2] * 32 + lane);
        uint2 u3 = __ldg(yp + (size_t)cs[3] * 32 + lane);
        uint2 u4 = __ldg(yp + (size_t)cs[4] * 32 + lane);
        uint2 u5 = __ldg(yp + (size_t)cs[5] * 32 + lane);
        uint2 u6 = __ldg(yp + (size_t)cs[6] * 32 + lane);
        uint2 u7 = __ldg(yp + (size_t)cs[7] * 32 + lane);
        uint2 u8 = __ldg(yp + (size_t)cs[8] * 32 + lane);
        uint2 u9 = __ldg(yp + (size_t)cs[9] * 32 + lane);
        uint2 uA = __ldg(yp + (size_t)cs[10] * 32 + lane);
        uint2 uB = __ldg(yp + (size_t)cs[11] * 32 + lane);
        uint2 uC = __ldg(yp + (size_t)cs[12] * 32 + lane);
        uint2 uD = __ldg(yp + (size_t)cs[13] * 32 + lane);
        uint2 uE = __ldg(yp + (size_t)cs[14] * 32 + lane);
        uint2 uF = __ldg(yp + (size_t)cs[15] * 32 + lane);
        acc_tree(a0, a1, u0.x, u1.x, u2.x, u3.x);
        acc_tree(a2, a3, u0.y, u1.y, u2.y, u3.y);
        acc_tree(b0, b1, u4.x, u5.x, u6.x, u7.x);
        acc_tree(b2, b3, u4.y, u5.y, u6.y, u7.y);
        acc_tree(c0, c1, u8.x, u9.x, uA.x, uB.x);
        acc_tree(c2, c3, u8.y, u9.y, uA.y, uB.y);
        acc_tree(e0, e1, uC.x, uD.x, uE.x, uF.x);
        acc_tree(e2, e3, uC.y, uD.y, uE.y, uF.y);
    }
    for (; j + 8 <= d; j += 8) {
        const int* cs = g_csr + start + j;
        uint2 u0 = __ldg(yp + (size_t)cs[0] * 32 + lane);
        uint2 u1 = __ldg(yp + (size_t)cs[1] * 32 + lane);
        uint2 u2 = __ldg(yp + (size_t)cs[2] * 32 + lane);
        uint2 u3 = __ldg(yp + (size_t)cs[3] * 32 + lane);
        uint2 u4 = __ldg(yp + (size_t)cs[4] * 32 + lane);
        uint2 u5 = __ldg(yp + (size_t)cs[5] * 32 + lane);
        uint2 u6 = __ldg(yp + (size_t)cs[6] * 32 + lane);
        uint2 u7 = __ldg(yp + (size_t)cs[7] * 32 + lane);
        acc_tree(a0, a1, u0.x, u1.x, u2.x, u3.x);
        acc_tree(a2, a3, u0.y, u1.y, u2.y, u3.y);
        acc_tree(b0, b1, u4.x, u5.x, u6.x, u7.x);
        acc_tree(b2, b3, u4.y, u5.y, u6.y, u7.y);
    }
    for (; j + 4 <= d; j += 4) {
        const int* cs = g_csr + start + j;
        uint2 u0 = __ldg(yp + (size_t)cs[0] * 32 + lane);
        uint2 u1 = __ldg(yp + (size_t)cs[1] * 32 + lane);
        uint2 u2 = __ldg(yp + (size_t)cs[2] * 32 + lane);
        uint2 u3 = __ldg(yp + (size_t)cs[3] * 32 + lane);
        acc_tree(a0, a1, u0.x, u1.x, u2.x, u3.x);
        acc_tree(a2, a3, u0.y, u1.y, u2.y, u3.y);
    }
    for (; j < d; j++) {
        int s = g_csr[start + j];
        acc_h4(a0, a1, a2, a3, __ldg(yp + (size_t)s * 32 + lane));
    }
    float inv = 1.0f / (float)(d + 1);
    float r0 = fmaxf((a0 + b0 + c0 + e0) * inv, 0.f);
    float r1 = fmaxf((a1 + b1 + c1 + e1) * inv, 0.f);
    float r2 = fmaxf((a2 + b2 + c2 + e2) * inv, 0.f);
    float r3 = fmaxf((a3 + b3 + c3 + e3) * inv, 0.f);
    __half2 p0 = __floats2half2_rn(r0, r1);
    __half2 p1 = __floats2half2_rn(r2, r3);
    uint2 w;
    w.x = *(uint32_t*)&p0;
    w.y = *(uint32_t*)&p1;
    ((uint2*)hout)[(size_t)node * 32 + lane] = w;
}

__global__ void agg64_kernel(float* __restrict__ hout) {
    int gid = blockIdx.x * blockDim.x + threadIdx.x;
    int node = gid >> 5;
    int lane = gid & 31;
    if (node >= N) return;
    const uint32_t* yp = (const uint32_t*)g_yh;
    size_t start = (size_t)node * PAD;
    int d = g_deg[node];

    float a0 = 0, a1 = 0, b0 = 0, b1 = 0;
    {
        uint32_t u = __ldg(yp + (size_t)node * 32 + lane);
        float2 f = __half22float2(*(__half2*)&u);
        a0 += f.x; a1 += f.y;
    }
    int j = 0;
    for (; j + 16 <= d; j += 16) {
        const int* cs = g_csr + start + j;
        uint32_t u[16];
#pragma unroll
        for (int q = 0; q < 16; q++)
            u[q] = __ldg(yp + (size_t)cs[q] * 32 + lane);
        acc_tree(a0, a1, u[0], u[1], u[2], u[3]);
        acc_tree(b0, b1, u[4], u[5], u[6], u[7]);
        acc_tree(a0, a1, u[8], u[9], u[10], u[11]);
        acc_tree(b0, b1, u[12], u[13], u[14], u[15]);
    }
    for (; j + 8 <= d; j += 8) {
        const int* cs = g_csr + start + j;
        uint32_t u[8];
#pragma unroll
        for (int q = 0; q < 8; q++)
            u[q] = __ldg(yp + (size_t)cs[q] * 32 + lane);
        acc_tree(a0, a1, u[0], u[1], u[2], u[3]);
        acc_tree(b0, b1, u[4], u[5], u[6], u[7]);
    }
    for (; j + 4 <= d; j += 4) {
        const int* cs = g_csr + start + j;
        uint32_t u0 = __ldg(yp + (size_t)cs[0] * 32 + lane);
        uint32_t u1 = __ldg(yp + (size_t)cs[1] * 32 + lane);
        uint32_t u2 = __ldg(yp + (size_t)cs[2] * 32 + lane);
        uint32_t u3 = __ldg(yp + (size_t)cs[3] * 32 + lane);
        acc_tree(a0, a1, u0, u1, u2, u3);
    }
    for (; j < d; j++) {
        int s = g_csr[start + j];
        uint32_t u = __ldg(yp + (size_t)s * 32 + lane);
        float2 f = __half22float2(*(__half2*)&u);
        a0 += f.x; a1 += f.y;
    }
    float inv = 1.0f / (float)(d + 1);
    float2 r;
    r.x = fmaxf((a0 + b0) * inv, 0.f);
    r.y = fmaxf((a1 + b1) * inv, 0.f);
    ((float2*)hout)[(size_t)node * 32 + lane] = r;
}

extern "C" void kernel_launch(void* const* d_in, const int* in_sizes, int n_in,
                              void* d_out, int out_size) {
    const float* x = (const float*)d_in[0];
    const int* ei = (const int*)d_in[1];
    const float* W1 = (const float*)d_in[2];
    const float* W2 = (const float*)d_in[3];
    const float* W3 = (const float*)d_in[4];
    float* out = (float*)d_out;

    const int4* src4 = (const int4*)ei;
    const int4* dst4 = (const int4*)(ei + E);

    const int ngrid = (N + 255) / 256;
    const int e4grid = (E / 4 + 255) / 256;   // 782
    const int agrid = (N * 32 + 255) / 256;
    const int ggrid = (N + 127) / 128;        // 391
    const int wgrid = (40960 + 255) / 256;

    __half* h16; cudaGetSymbolAddress((void**)&h16, g_h16);
    __half* yh;  cudaGetSymbolAddress((void**)&yh, g_yh);
    __half* w16; cudaGetSymbolAddress((void**)&w16, g_W16);

    const int SMEM128 = A_TILE + 128 * PITCH * 2;  // 69632
    const int SMEM64  = A_TILE + 64 * PITCH * 2;   // 52224

    // one-time resources (created on the uncaptured correctness call)
    static cudaStream_t s2 = nullptr;
    static cudaEvent_t ev_fork = nullptr, ev_join = nullptr;
    if (!s2) {
        cudaStreamCreateWithFlags(&s2, cudaStreamNonBlocking);
        cudaEventCreateWithFlags(&ev_fork, cudaEventDisableTiming);
        cudaEventCreateWithFlags(&ev_join, cudaEventDisableTiming);
        cudaFuncSetAttribute((const void*)mma_gemm_kernel<128, true>,
                             cudaFuncAttributeMaxDynamicSharedMemorySize, SMEM128);
        cudaFuncSetAttribute((const void*)mma_gemm_kernel<128, false>,
                             cudaFuncAttributeMaxDynamicSharedMemorySize, SMEM128);
        cudaFuncSetAttribute((const void*)mma_gemm_kernel<64, false>,
                             cudaFuncAttributeMaxDynamicSharedMemorySize, SMEM64);
    }

    // fork: CSR build on s2, W-convert + layer-1 GEMM on main stream
    cudaEventRecord(ev_fork, 0);
    cudaStreamWaitEvent(s2, ev_fork, 0);

    zero_deg_kernel<<<ngrid, 256, 0, s2>>>();
    fill_pad_kernel<<<e4grid, 256, 0, s2>>>(src4, dst4);
    cudaEventRecord(ev_join, s2);

    wsplit_kernel<<<wgrid, 256>>>(W1, W2, W3);
    mma_gemm_kernel<128, true><<<ggrid, 256, SMEM128>>>(x, w16, yh);

    // join: agg needs both CSR and yh
    cudaStreamWaitEvent(0, ev_join, 0);

    // Layer 1 aggregation
    agg128_kernel<<<agrid, 256>>>(h16);

    // Layer 2
    mma_gemm_kernel<128, false><<<ggrid, 256, SMEM128>>>(h16, w16 + 16384, yh);
    agg128_kernel<<<agrid, 256>>>(h16);

    // Layer 3 (64-dim)
    mma_gemm_kernel<64, false><<<ggrid, 256, SMEM64>>>(h16, w16 + 32768, yh);
    agg64_kernel<<<agrid, 256>>>(out);
}

// round 16
// speedup vs baseline: 1.0377x; 1.0377x over previous
#include <cuda_runtime.h>
#include <cuda_fp16.h>
#include <cstdint>

constexpr int N = 50000;     // nodes
constexpr int E = 800000;    // edges
constexpr int K = 128;       // feature dim
constexpr int PAD = 96;      // padded CSR row stride

// ---------------- device scratch ----------------
__device__ __align__(16) __half g_yh[(size_t)N * K];   // GEMM output (fp16)
__device__ __align__(16) __half g_h16[(size_t)N * K];  // activations (fp16)
__device__ int   g_deg[N];
__device__ int   g_csr[(size_t)N * PAD];               // padded CSR (19.2 MB)
// W fp16: W1(16384) W2(16384) W3(8192)
__device__ __align__(16) __half g_W16[40960];

// ---------------- helpers ----------------
__device__ __forceinline__ uint32_t smem_u32(const void* p) {
    uint32_t a;
    asm("{ .reg .u64 t; cvta.to.shared.u64 t, %1; cvt.u32.u64 %0, t; }" : "=r"(a) : "l"(p));
    return a;
}

#define LDMX4(r0, r1, r2, r3, addr)                                            \
    asm volatile("ldmatrix.sync.aligned.m8n8.x4.shared.b16 {%0,%1,%2,%3}, [%4];" \
                 : "=r"(r0), "=r"(r1), "=r"(r2), "=r"(r3) : "r"(addr))

#define MMAF16(d, a, b)                                                         \
    asm volatile("mma.sync.aligned.m16n8k16.row.col.f32.f16.f16.f32 "            \
                 "{%0,%1,%2,%3}, {%4,%5,%6,%7}, {%8,%9}, {%0,%1,%2,%3};"         \
                 : "+f"((d)[0]), "+f"((d)[1]), "+f"((d)[2]), "+f"((d)[3])        \
                 : "r"((a)[0]), "r"((a)[1]), "r"((a)[2]), "r"((a)[3]),           \
                   "r"((b)[0]), "r"((b)[1]))

// ---------------- fused: W convert + deg zero ----------------
__global__ void wsplit_zero_kernel(const float* __restrict__ W1,
                                   const float* __restrict__ W2,
                                   const float* __restrict__ W3) {
    int i = blockIdx.x * blockDim.x + threadIdx.x;
    if (i < N) g_deg[i] = 0;
    if (i < 40960) {
        float v;
        if (i < 16384) v = W1[i];
        else if (i < 32768) v = W2[i - 16384];
        else v = W3[i - 32768];
        g_W16[i] = __float2half_rn(v);
    }
}

// single edge pass: degree count + padded CSR scatter in one atomic
__global__ void fill_pad_kernel(const int4* __restrict__ src4,
                                const int4* __restrict__ dst4) {
    int t = blockIdx.x * blockDim.x + threadIdx.x;
    if (t < E / 4) {
        int4 d = __ldg(dst4 + t);
        int4 s = __ldg(src4 + t);
        int p0 = atomicAdd(&g_deg[d.x], 1);
        int p1 = atomicAdd(&g_deg[d.y], 1);
        int p2 = atomicAdd(&g_deg[d.z], 1);
        int p3 = atomicAdd(&g_deg[d.w], 1);
        if (p0 < PAD) g_csr[(size_t)d.x * PAD + p0] = s.x;
        if (p1 < PAD) g_csr[(size_t)d.y * PAD + p1] = s.y;
        if (p2 < PAD) g_csr[(size_t)d.z * PAD + p2] = s.z;
        if (p3 < PAD) g_csr[(size_t)d.w * PAD + p3] = s.w;
    }
}

// ---------------- HMMA GEMM: Yh = fp16( H @ W^T ), single fp16 W ----------------
constexpr int PITCH = 136;               // fp16 elems per smem row (17x16B)
constexpr int A_TILE = 128 * PITCH * 2;  // 34816 bytes

template <int DOUT, bool SRC32>
__global__ __launch_bounds__(256)
void mma_gemm_kernel(const void* __restrict__ Hin,
                     const __half* __restrict__ Wm,
                     __half* __restrict__ Yh) {
    constexpr int OFF_A = 0;
    constexpr int OFF_B = A_TILE;
    constexpr int NT = DOUT / 16;
    constexpr int NG = NT / 2;

    extern __shared__ char smem[];
    uint32_t sb = smem_u32(smem);
    int tid = threadIdx.x;
    int lane = tid & 31;
    int wid = tid >> 5;
    int wm = wid & 3;
    int wn = wid >> 2;
    int base = blockIdx.x * 128;

    // ---- A prologue (vectorized 16B loads) ----
    if (SRC32) {
        // 128 rows x 32 float4 per row = 4096 float4s
        const float4* xp = (const float4*)Hin;
        for (int p = tid; p < 128 * 32; p += 256) {
            int r = p >> 5;
            int c4 = p & 31;         // float4 index within row
            int node = base + r;
            float4 v = make_float4(0.f, 0.f, 0.f, 0.f);
            if (node < N) v = __ldg(xp + (size_t)node * 32 + c4);
            __half2 h0 = __floats2half2_rn(v.x, v.y);
            __half2 h1 = __floats2half2_rn(v.z, v.w);
            uint2 w;
            w.x = *(uint32_t*)&h0;
            w.y = *(uint32_t*)&h1;
            *(uint2*)(smem + OFF_A + (r * PITCH + c4 * 4) * 2) = w;
        }
    } else {
        // 128 rows x 16 uint4 per row = 2048 uint4s
        const uint4* hp = (const uint4*)Hin;
        for (int p = tid; p < 128 * 16; p += 256) {
            int r = p >> 4;
            int c8 = p & 15;         // uint4 index (8 halves)
            int node = base + r;
            uint4 w = make_uint4(0, 0, 0, 0);
            if (node < N) w = __ldg(hp + (size_t)node * 16 + c8);
            *(uint4*)(smem + OFF_A + (r * PITCH + c8 * 8) * 2) = w;
        }
    }
    // ---- B prologue (16B loads) ----
    {
        const uint4* wp = (const uint4*)Wm;
        for (int p = tid; p < DOUT * 16; p += 256) {
            int r = p >> 4;
            int c8 = p & 15;
            uint4 w = __ldg(wp + p);
            *(uint4*)(smem + OFF_B + (r * PITCH + c8 * 8) * 2) = w;
        }
    }
    __syncthreads();

    int m = lane >> 3;
    int lr = lane & 7;
    int rb = wm * 32;
    int nb = wn * (DOUT / 2);

    uint32_t aoff0 = (uint32_t)(((rb + lr + (m & 1) * 8) * PITCH + (m >> 1) * 8) * 2);
    uint32_t aoff1 = aoff0 + 16 * PITCH * 2;
    uint32_t boff[NG];
#pragma unroll
    for (int g = 0; g < NG; g++)
        boff[g] = (uint32_t)(((nb + 16 * g + lr + (m >> 1) * 8) * PITCH + (m & 1) * 8) * 2);

    float acc[2][NT][4];
#pragma unroll
    for (int mt = 0; mt < 2; mt++)
#pragma unroll
        for (int nt = 0; nt < NT; nt++)
#pragma unroll
            for (int q = 0; q < 4; q++) acc[mt][nt][q] = 0.f;

#pragma unroll
    for (int j = 0; j < 8; j++) {
        uint32_t kb = j * 32;
        uint32_t a[2][4], b[NT][2];
        LDMX4(a[0][0], a[0][1], a[0][2], a[0][3], sb + OFF_A + aoff0 + kb);
        LDMX4(a[1][0], a[1][1], a[1][2], a[1][3], sb + OFF_A + aoff1 + kb);
#pragma unroll
        for (int g = 0; g < NG; g++) {
            LDMX4(b[2 * g][0], b[2 * g][1], b[2 * g + 1][0], b[2 * g + 1][1],
                  sb + OFF_B + boff[g] + kb);
        }
#pragma unroll
        for (int mt = 0; mt < 2; mt++)
#pragma unroll
            for (int nt = 0; nt < NT; nt++)
                MMAF16(acc[mt][nt], a[mt], b[nt]);
    }

    int r0 = base + rb + (lane >> 2);
#pragma unroll
    for (int mt = 0; mt < 2; mt++) {
        int row = r0 + 16 * mt;
#pragma unroll
        for (int nt = 0; nt < NT; nt++) {
            int col = nb + 8 * nt + 2 * (lane & 3);
            if (row < N) {
                __half2 h = __floats2half2_rn(acc[mt][nt][0], acc[mt][nt][1]);
                *(__half2*)(Yh + (size_t)row * DOUT + col) = h;
            }
            if (row + 8 < N) {
                __half2 h = __floats2half2_rn(acc[mt][nt][2], acc[mt][nt][3]);
                *(__half2*)(Yh + (size_t)(row + 8) * DOUT + col) = h;
            }
        }
    }
}

// ---------------- aggregation ----------------
__device__ __forceinline__ void acc_h4(float& a0, float& a1, float& a2, float& a3, uint2 u) {
    float2 f0 = __half22float2(*(__half2*)&u.x);
    float2 f1 = __half22float2(*(__half2*)&u.y);
    a0 += f0.x; a1 += f0.y; a2 += f1.x; a3 += f1.y;
}

__device__ __forceinline__ void acc_tree(float& a0, float& a1,
                                         uint32_t w0, uint32_t w1,
                                         uint32_t w2, uint32_t w3) {
    __half2 h0 = __hadd2(*(__half2*)&w0, *(__half2*)&w1);
    __half2 h1 = __hadd2(*(__half2*)&w2, *(__half2*)&w3);
    __half2 h  = __hadd2(h0, h1);
    float2 f = __half22float2(h);
    a0 += f.x; a1 += f.y;
}

// 128-dim: fp32 accumulate (measured faster than fp16-tree: 31.6 vs 34.2 us)
__global__ void agg128_kernel(__half* __restrict__ hout) {
    int gid = blockIdx.x * blockDim.x + threadIdx.x;
    int node = gid >> 5;
    int lane = gid & 31;
    if (node >= N) return;
    const uint2* yp = (const uint2*)g_yh;
    size_t start = (size_t)node * PAD;
    int d = g_deg[node];

    float a0 = 0, a1 = 0, a2 = 0, a3 = 0;
    float b0 = 0, b1 = 0, b2 = 0, b3 = 0;
    float c0 = 0, c1 = 0, c2 = 0, c3 = 0;
    float e0 = 0, e1 = 0, e2 = 0, e3 = 0;

    acc_h4(a0, a1, a2, a3, __ldg(yp + (size_t)node * 32 + lane));

    int j = 0;
    for (; j + 16 <= d; j += 16) {
        const int* cs = g_csr + start + j;
        uint2 u0 = __ldg(yp + (size_t)cs[0] * 32 + lane);
        uint2 u1 = __ldg(yp + (size_t)cs[1] * 32 + lane);
        uint2 u2 = __ldg(yp + (size_t)cs[2] * 32 + lane);
        uint2 u3 = __ldg(yp + (size_t)cs[3] * 32 + lane);
        uint2 u4 = __ldg(yp + (size_t)cs[4] * 32 + lane);
        uint2 u5 = __ldg(yp + (size_t)cs[5] * 32 + lane);
        uint2 u6 = __ldg(yp + (size_t)cs[6] * 32 + lane);
        uint2 u7 = __ldg(yp + (size_t)cs[7] * 32 + lane);
        uint2 u8 = __ldg(yp + (size_t)cs[8] * 32 + lane);
        uint2 u9 = __ldg(yp + (size_t)cs[9] * 32 + lane);
        uint2 uA = __ldg(yp + (size_t)cs[10] * 32 + lane);
        uint2 uB = __ldg(yp + (size_t)cs[11] * 32 + lane);
        uint2 uC = __ldg(yp + (size_t)cs[12] * 32 + lane);
        uint2 uD = __ldg(yp + (size_t)cs[13] * 32 + lane);
        uint2 uE = __ldg(yp + (size_t)cs[14] * 32 + lane);
        uint2 uF = __ldg(yp + (size_t)cs[15] * 32 + lane);
        acc_h4(a0, a1, a2, a3, u0);
        acc_h4(b0, b1, b2, b3, u1);
        acc_h4(c0, c1, c2, c3, u2);
        acc_h4(e0, e1, e2, e3, u3);
        acc_h4(a0, a1, a2, a3, u4);
        acc_h4(b0, b1, b2, b3, u5);
        acc_h4(c0, c1, c2, c3, u6);
        acc_h4(e0, e1, e2, e3, u7);
        acc_h4(a0, a1, a2, a3, u8);
        acc_h4(b0, b1, b2, b3, u9);
        acc_h4(c0, c1, c2, c3, uA);
        acc_h4(e0, e1, e2, e3, uB);
        acc_h4(a0, a1, a2, a3, uC);
        acc_h4(b0, b1, b2, b3, uD);
        acc_h4(c0, c1, c2, c3, uE);
        acc_h4(e0, e1, e2, e3, uF);
    }
    for (; j + 8 <= d; j += 8) {
        const int* cs = g_csr + start + j;
        uint2 u0 = __ldg(yp + (size_t)cs[0] * 32 + lane);
        uint2 u1 = __ldg(yp + (size_t)cs[1] * 32 + lane);
        uint2 u2 = __ldg(yp + (size_t)cs[2] * 32 + lane);
        uint2 u3 = __ldg(yp + (size_t)cs[3] * 32 + lane);
        uint2 u4 = __ldg(yp + (size_t)cs[4] * 32 + lane);
        uint2 u5 = __ldg(yp + (size_t)cs[5] * 32 + lane);
        uint2 u6 = __ldg(yp + (size_t)cs[6] * 32 + lane);
        uint2 u7 = __ldg(yp + (size_t)cs[7] * 32 + lane);
        acc_h4(a0, a1, a2, a3, u0);
        acc_h4(b0, b1, b2, b3, u1);
        acc_h4(c0, c1, c2, c3, u2);
        acc_h4(e0, e1, e2, e3, u3);
        acc_h4(a0, a1, a2, a3, u4);
        acc_h4(b0, b1, b2, b3, u5);
        acc_h4(c0, c1, c2, c3, u6);
        acc_h4(e0, e1, e2, e3, u7);
    }
    for (; j + 4 <= d; j += 4) {
        const int* cs = g_csr + start + j;
        uint2 u0 = __ldg(yp + (size_t)cs[0] * 32 + lane);
        uint2 u1 = __ldg(yp + (size_t)cs[1] * 32 + lane);
        uint2 u2 = __ldg(yp + (size_t)cs[2] * 32 + lane);
        uint2 u3 = __ldg(yp + (size_t)cs[3] * 32 + lane);
        acc_h4(a0, a1, a2, a3, u0);
        acc_h4(b0, b1, b2, b3, u1);
        acc_h4(c0, c1, c2, c3, u2);
        acc_h4(e0, e1, e2, e3, u3);
    }
    for (; j < d; j++) {
        int s = g_csr[start + j];
        acc_h4(a0, a1, a2, a3, __ldg(yp + (size_t)s * 32 + lane));
    }
    float inv = 1.0f / (float)(d + 1);
    float r0 = fmaxf((a0 + b0 + c0 + e0) * inv, 0.f);
    float r1 = fmaxf((a1 + b1 + c1 + e1) * inv, 0.f);
    float r2 = fmaxf((a2 + b2 + c2 + e2) * inv, 0.f);
    float r3 = fmaxf((a3 + b3 + c3 + e3) * inv, 0.f);
    __half2 p0 = __floats2half2_rn(r0, r1);
    __half2 p1 = __floats2half2_rn(r2, r3);
    uint2 w;
    w.x = *(uint32_t*)&p0;
    w.y = *(uint32_t*)&p1;
    ((uint2*)hout)[(size_t)node * 32 + lane] = w;
}

// 64-dim final: fp16 tree (measured win here), fp32 out
__global__ void agg64_kernel(float* __restrict__ hout) {
    int gid = blockIdx.x * blockDim.x + threadIdx.x;
    int node = gid >> 5;
    int lane = gid & 31;
    if (node >= N) return;
    const uint32_t* yp = (const uint32_t*)g_yh;
    size_t start = (size_t)node * PAD;
    int d = g_deg[node];

    float a0 = 0, a1 = 0, b0 = 0, b1 = 0;
    {
        uint32_t u = __ldg(yp + (size_t)node * 32 + lane);
        float2 f = __half22float2(*(__half2*)&u);
        a0 += f.x; a1 += f.y;
    }
    int j = 0;
    for (; j + 16 <= d; j += 16) {
        const int* cs = g_csr + start + j;
        uint32_t u[16];
#pragma unroll
        for (int q = 0; q < 16; q++)
            u[q] = __ldg(yp + (size_t)cs[q] * 32 + lane);
        acc_tree(a0, a1, u[0], u[1], u[2], u[3]);
        acc_tree(b0, b1, u[4], u[5], u[6], u[7]);
        acc_tree(a0, a1, u[8], u[9], u[10], u[11]);
        acc_tree(b0, b1, u[12], u[13], u[14], u[15]);
    }
    for (; j + 8 <= d; j += 8) {
        const int* cs = g_csr + start + j;
        uint32_t u[8];
#pragma unroll
        for (int q = 0; q < 8; q++)
            u[q] = __ldg(yp + (size_t)cs[q] * 32 + lane);
        acc_tree(a0, a1, u[0], u[1], u[2], u[3]);
        acc_tree(b0, b1, u[4], u[5], u[6], u[7]);
    }
    for (; j + 4 <= d; j += 4) {
        const int* cs = g_csr + start + j;
        uint32_t u0 = __ldg(yp + (size_t)cs[0] * 32 + lane);
        uint32_t u1 = __ldg(yp + (size_t)cs[1] * 32 + lane);
        uint32_t u2 = __ldg(yp + (size_t)cs[2] * 32 + lane);
        uint32_t u3 = __ldg(yp + (size_t)cs[3] * 32 + lane);
        acc_tree(a0, a1, u0, u1, u2, u3);
    }
    for (; j < d; j++) {
        int s = g_csr[start + j];
        uint32_t u = __ldg(yp + (size_t)s * 32 + lane);
        float2 f = __half22float2(*(__half2*)&u);
        a0 += f.x; a1 += f.y;
    }
    float inv = 1.0f / (float)(d + 1);
    float2 r;
    r.x = fmaxf((a0 + b0) * inv, 0.f);
    r.y = fmaxf((a1 + b1) * inv, 0.f);
    ((float2*)hout)[(size_t)node * 32 + lane] = r;
}

extern "C" void kernel_launch(void* const* d_in, const int* in_sizes, int n_in,
                              void* d_out, int out_size) {
    const float* x = (const float*)d_in[0];
    const int* ei = (const int*)d_in[1];
    const float* W1 = (const float*)d_in[2];
    const float* W2 = (const float*)d_in[3];
    const float* W3 = (const float*)d_in[4];
    float* out = (float*)d_out;

    const int4* src4 = (const int4*)ei;
    const int4* dst4 = (const int4*)(ei + E);

    const int ngrid = (N + 255) / 256;
    const int e4grid = (E / 4 + 255) / 256;   // 782
    const int agrid = (N * 32 + 255) / 256;
    const int ggrid = (N + 127) / 128;        // 391

    __half* h16; cudaGetSymbolAddress((void**)&h16, g_h16);
    __half* yh;  cudaGetSymbolAddress((void**)&yh, g_yh);
    __half* w16; cudaGetSymbolAddress((void**)&w16, g_W16);

    const int SMEM128 = A_TILE + 128 * PITCH * 2;  // 69632
    const int SMEM64  = A_TILE + 64 * PITCH * 2;   // 52224
    cudaFuncSetAttribute((const void*)mma_gemm_kernel<128, true>,
                         cudaFuncAttributeMaxDynamicSharedMemorySize, SMEM128);
    cudaFuncSetAttribute((const void*)mma_gemm_kernel<128, false>,
                         cudaFuncAttributeMaxDynamicSharedMemorySize, SMEM128);
    cudaFuncSetAttribute((const void*)mma_gemm_kernel<64, false>,
                         cudaFuncAttributeMaxDynamicSharedMemorySize, SMEM64);

    // CSR build (single edge pass) + weight convert
    wsplit_zero_kernel<<<ngrid, 256>>>(W1, W2, W3);
    fill_pad_kernel<<<e4grid, 256>>>(src4, dst4);

    // Layer 1
    mma_gemm_kernel<128, true><<<ggrid, 256, SMEM128>>>(x, w16, yh);
    agg128_kernel<<<agrid, 256>>>(h16);

    // Layer 2
    mma_gemm_kernel<128, false><<<ggrid, 256, SMEM128>>>(h16, w16 + 16384, yh);
    agg128_kernel<<<agrid, 256>>>(h16);

    // Layer 3 (64-dim)
    mma_gemm_kernel<64, false><<<ggrid, 256, SMEM64>>>(h16, w16 + 32768, yh);
    agg64_kernel<<<agrid, 256>>>(out);
}